// round 13
// baseline (speedup 1.0000x reference)
#include <cuda_runtime.h>
#include <cstdint>

// Problem constants (fixed shapes for this problem instance).
#define NMAX   100000
#define EMAX   1600000
#define INDIM  512
#define HID    64
#define NCLS   16

// ---------------- scratch (device globals; no allocation allowed) ----------
__device__ __align__(256) float g_dis [NMAX];                    // deg -> rsqrt(deg)
__device__ __align__(256) float g_norm[EMAX];                    // per-edge norm
__device__ __align__(256) uint32_t g_Hb [(size_t)NMAX * HID / 2];  // x@W1, bf16x2 packed
__device__ __align__(256) float g_O1 [(size_t)NMAX * HID];       // aggregated layer-1 (fp32)
__device__ __align__(256) uint32_t g_H2b[(size_t)NMAX * NCLS / 2]; // relu(O1+b1)@W2, bf16x2
__device__ __align__(256) float g_O2 [(size_t)NMAX * NCLS];      // aggregated layer-2 (fp32)
// W1^T as packed bf16x2 over k-pairs: [n=0..63][kpair=0..255]
__device__ __align__(256) uint32_t g_Wbhi[(size_t)HID * INDIM / 2];

// pack two floats as bf16x2: result.lo16 = bf16(lo), result.hi16 = bf16(hi)
__device__ __forceinline__ uint32_t bf16x2(float hi, float lo) {
    uint32_t r;
    asm("cvt.rn.bf16x2.f32 %0, %1, %2;" : "=r"(r) : "f"(hi), "f"(lo));
    return r;
}
// unpack: lo element = bits<<16, hi element = bits&0xFFFF0000
__device__ __forceinline__ float bf_lo(uint32_t u) { return __uint_as_float(u << 16); }
__device__ __forceinline__ float bf_hi(uint32_t u) { return __uint_as_float(u & 0xFFFF0000u); }

// ---------------- prep: deg init (self-loop) + W1 bf16 transpose/pack ------
__global__ void k_prep(const float* __restrict__ W1, int n) {
    int i = blockIdx.x * blockDim.x + threadIdx.x;
    if (i < n) g_dis[i] = 1.0f;                       // self-loop weight
    if (i < HID * INDIM / 2) {                        // W1^T bf16 packed
        int c  = i >> 8;                              // output column 0..63
        int kp = i & 255;                             // k-pair 0..255
        float v0 = W1[(size_t)(2 * kp)     * HID + c];
        float v1 = W1[(size_t)(2 * kp + 1) * HID + c];
        g_Wbhi[i] = bf16x2(v1, v0);
    }
}

__global__ void k_deg_acc(const int* __restrict__ dst, const float* __restrict__ w, int E) {
    int q = blockIdx.x * blockDim.x + threadIdx.x;
    int base = q * 4;
    if (base + 3 < E) {
        int4   d = *(const int4*)&dst[base];
        float4 v = *(const float4*)&w[base];
        atomicAdd(&g_dis[d.x], v.x);
        atomicAdd(&g_dis[d.y], v.y);
        atomicAdd(&g_dis[d.z], v.z);
        atomicAdd(&g_dis[d.w], v.w);
    } else {
        for (int e = base; e < E; e++) atomicAdd(&g_dis[dst[e]], w[e]);
    }
}

__global__ void k_deg_fin(int n) {
    int i = blockIdx.x * blockDim.x + threadIdx.x;
    if (i < n) g_dis[i] = rsqrtf(g_dis[i]);
}

// 8 edges per thread: 16 independent L2 gathers in flight (latency-bound kernel)
__global__ void k_norm(const int* __restrict__ src, const int* __restrict__ dst,
                       const float* __restrict__ w, int E) {
    int q = blockIdx.x * blockDim.x + threadIdx.x;
    int base = q * 8;
    if (base + 7 < E) {
        int4   s0 = *(const int4*)&src[base];
        int4   s1 = *(const int4*)&src[base + 4];
        int4   d0 = *(const int4*)&dst[base];
        int4   d1 = *(const int4*)&dst[base + 4];
        float4 v0 = *(const float4*)&w[base];
        float4 v1 = *(const float4*)&w[base + 4];
        float a0 = g_dis[s0.x], a1 = g_dis[s0.y], a2 = g_dis[s0.z], a3 = g_dis[s0.w];
        float a4 = g_dis[s1.x], a5 = g_dis[s1.y], a6 = g_dis[s1.z], a7 = g_dis[s1.w];
        float b0 = g_dis[d0.x], b1 = g_dis[d0.y], b2 = g_dis[d0.z], b3 = g_dis[d0.w];
        float b4 = g_dis[d1.x], b5 = g_dis[d1.y], b6 = g_dis[d1.z], b7 = g_dis[d1.w];
        float4 o0 = make_float4(a0 * v0.x * b0, a1 * v0.y * b1, a2 * v0.z * b2, a3 * v0.w * b3);
        float4 o1 = make_float4(a4 * v1.x * b4, a5 * v1.y * b5, a6 * v1.z * b6, a7 * v1.w * b7);
        *(float4*)&g_norm[base]     = o0;
        *(float4*)&g_norm[base + 4] = o1;
    } else {
        for (int e = base; e < E; e++) g_norm[e] = g_dis[src[e]] * w[e] * g_dis[dst[e]];
    }
}

// ---------------- GEMM1 via mma.sync bf16 m16n8k16 (1-term, pure bf16) -----
// D[128,64] = bf16(A)[128,512] * bf16(B)[64,512]^T, fp32 accum.
// 256 threads = 8 warps as 4(m) x 2(n); warp tile 32x32 = 2x4 mma tiles of 16x8.
// Smem rows padded to 12 words: fragment pattern gid*12 + tig(+4) is
// bank-conflict-free (12g+t mod 32 distinct for g<8, t<8).
// Double-buffered: LDG(c+1) -> compute(c) -> STS(c+1), 1 syncthreads/chunk.
#define GM  128
#define NCH (INDIM / 16)           // 32 chunks of k=16

__device__ __forceinline__ void mma_bf16(float* c, const uint32_t* a, const uint32_t* b) {
    asm volatile(
        "mma.sync.aligned.m16n8k16.row.col.f32.bf16.bf16.f32 "
        "{%0,%1,%2,%3}, {%4,%5,%6,%7}, {%8,%9}, {%0,%1,%2,%3};"
        : "+f"(c[0]), "+f"(c[1]), "+f"(c[2]), "+f"(c[3])
        : "r"(a[0]), "r"(a[1]), "r"(a[2]), "r"(a[3]), "r"(b[0]), "r"(b[1]));
}

__global__ __launch_bounds__(256)
void k_gemm1_mma(const float* __restrict__ X, int Nrows) {
    __shared__ uint32_t Ah[2][GM][12];
    __shared__ uint32_t Bh[2][HID][12];

    const int tid  = threadIdx.x;
    const int lane = tid & 31;
    const int wid  = tid >> 5;
    const int wm   = wid >> 1;          // 0..3
    const int wn   = wid & 1;           // 0..1
    const int gid  = lane >> 2;         // groupID
    const int tig  = lane & 3;          // threadID in group
    const int rowBase = blockIdx.x * GM;

    // staging geometry (chunk-independent)
    const int ra = tid >> 2;            // A row for p=0 (p=1: +64)
    const int kq = tid & 3;             // float4 slot within k16
    const int rb = tid >> 2;            // B row 0..63
    const int pg = tid & 3;             // B k-pair group (2 pairs each)

    float C[2][4][4];
    #pragma unroll
    for (int mt = 0; mt < 2; mt++)
        #pragma unroll
        for (int nt = 0; nt < 4; nt++)
            #pragma unroll
            for (int q = 0; q < 4; q++) C[mt][nt][q] = 0.0f;

    float4 va[2];
    uint2  vbh;

    // ---- prologue: load + stage chunk 0 ----
    #pragma unroll
    for (int p = 0; p < 2; p++) {
        int grow = rowBase + ra + p * 64;
        va[p] = make_float4(0.f, 0.f, 0.f, 0.f);
        if (grow < Nrows) va[p] = *(const float4*)&X[(size_t)grow * INDIM + kq * 4];
    }
    vbh = *(const uint2*)&g_Wbhi[(size_t)rb * (INDIM / 2) + pg * 2];
    #pragma unroll
    for (int p = 0; p < 2; p++) {
        uint32_t h0 = bf16x2(va[p].y, va[p].x);
        uint32_t h1 = bf16x2(va[p].w, va[p].z);
        *(uint2*)&Ah[0][ra + p * 64][kq * 2] = make_uint2(h0, h1);
    }
    *(uint2*)&Bh[0][rb][pg * 2] = vbh;
    __syncthreads();

    for (int c = 0; c < NCH; c++) {
        const int buf = c & 1;
        // ---- prefetch chunk c+1 into registers ----
        if (c + 1 < NCH) {
            const int k0n = (c + 1) * 16;
            #pragma unroll
            for (int p = 0; p < 2; p++) {
                int grow = rowBase + ra + p * 64;
                va[p] = make_float4(0.f, 0.f, 0.f, 0.f);
                if (grow < Nrows)
                    va[p] = *(const float4*)&X[(size_t)grow * INDIM + k0n + kq * 4];
            }
            vbh = *(const uint2*)&g_Wbhi[(size_t)rb * (INDIM / 2) + (c + 1) * 8 + pg * 2];
        }

        // ---- compute chunk c ----
        {
            const uint32_t (*pA)[12] = Ah[buf];
            const uint32_t (*pBh)[12] = Bh[buf];
            uint32_t ah[2][4];
            #pragma unroll
            for (int mt = 0; mt < 2; mt++) {
                int r0 = wm * 32 + mt * 16 + gid;
                ah[mt][0] = pA[r0][tig];
                ah[mt][1] = pA[r0 + 8][tig];
                ah[mt][2] = pA[r0][tig + 4];
                ah[mt][3] = pA[r0 + 8][tig + 4];
            }
            uint32_t bhf[4][2];
            #pragma unroll
            for (int nt = 0; nt < 4; nt++) {
                int cb = wn * 32 + nt * 8 + gid;
                bhf[nt][0] = pBh[cb][tig]; bhf[nt][1] = pBh[cb][tig + 4];
            }
            #pragma unroll
            for (int mt = 0; mt < 2; mt++)
                #pragma unroll
                for (int nt = 0; nt < 4; nt++)
                    mma_bf16(C[mt][nt], ah[mt], bhf[nt]);
        }

        // ---- stage chunk c+1 ----
        if (c + 1 < NCH) {
            const int nb = buf ^ 1;
            #pragma unroll
            for (int p = 0; p < 2; p++) {
                uint32_t h0 = bf16x2(va[p].y, va[p].x);
                uint32_t h1 = bf16x2(va[p].w, va[p].z);
                *(uint2*)&Ah[nb][ra + p * 64][kq * 2] = make_uint2(h0, h1);
            }
            *(uint2*)&Bh[nb][rb][pg * 2] = vbh;
        }
        __syncthreads();
    }

    // ---- epilogue: Hb (bf16 packed) and O1 = H * dis^2 (self-loop init) ----
    #pragma unroll
    for (int mt = 0; mt < 2; mt++) {
        int r0 = rowBase + wm * 32 + mt * 16 + gid;
        int r1 = r0 + 8;
        if (r0 < Nrows) {
            float d = g_dis[r0]; float sn = d * d;
            uint32_t* hrow = &g_Hb[(size_t)r0 * (HID / 2)];
            float*    orow = &g_O1[(size_t)r0 * HID];
            #pragma unroll
            for (int nt = 0; nt < 4; nt++) {
                int col = wn * 32 + nt * 8 + tig * 2;
                float2 v = make_float2(C[mt][nt][0], C[mt][nt][1]);
                hrow[col >> 1] = bf16x2(v.y, v.x);
                *(float2*)&orow[col] = make_float2(v.x * sn, v.y * sn);
            }
        }
        if (r1 < Nrows) {
            float d = g_dis[r1]; float sn = d * d;
            uint32_t* hrow = &g_Hb[(size_t)r1 * (HID / 2)];
            float*    orow = &g_O1[(size_t)r1 * HID];
            #pragma unroll
            for (int nt = 0; nt < 4; nt++) {
                int col = wn * 32 + nt * 8 + tig * 2;
                float2 v = make_float2(C[mt][nt][2], C[mt][nt][3]);
                hrow[col >> 1] = bf16x2(v.y, v.x);
                *(float2*)&orow[col] = make_float2(v.x * sn, v.y * sn);
            }
        }
    }
}

// ---------------- edge aggregation, 64 features (8 lanes per edge) ---------
// Gather bf16-packed H (16B/lane = 8 features), scatter fp32 REDs.
__device__ __forceinline__ void red_add_v4(float* addr, float a, float b, float c, float d) {
    asm volatile("red.global.add.v4.f32 [%0], {%1, %2, %3, %4};"
                 :: "l"(addr), "f"(a), "f"(b), "f"(c), "f"(d) : "memory");
}

__global__ __launch_bounds__(256)
void k_agg64(const int* __restrict__ src, const int* __restrict__ dst, int E) {
    int t = blockIdx.x * blockDim.x + threadIdx.x;
    int e = t >> 3;
    if (e >= E) return;
    int lane = t & 7;
    int s = src[e];
    int d = dst[e];
    float nr = g_norm[e];
    uint4 p = *(const uint4*)&g_Hb[(size_t)s * (HID / 2) + lane * 4];
    float* base = &g_O1[(size_t)d * HID + lane * 8];
    red_add_v4(base,     bf_lo(p.x) * nr, bf_hi(p.x) * nr, bf_lo(p.y) * nr, bf_hi(p.y) * nr);
    red_add_v4(base + 4, bf_lo(p.z) * nr, bf_hi(p.z) * nr, bf_lo(p.w) * nr, bf_hi(p.w) * nr);
}

// ---------------- layer 2: H2 = relu(O1+b1) @ W2 ; O2 = H2 * selfnorm ------
__global__ __launch_bounds__(256)
void k_layer2(const float* __restrict__ b1, const float* __restrict__ W2, int Nn) {
    __shared__ float Ws[HID * NCLS];
    __shared__ float bs[HID];
    for (int i = threadIdx.x; i < HID * NCLS; i += blockDim.x) Ws[i] = W2[i];
    if (threadIdx.x < HID) bs[threadIdx.x] = b1[threadIdx.x];
    __syncthreads();

    int n = blockIdx.x * blockDim.x + threadIdx.x;
    if (n >= Nn) return;

    float acc[NCLS];
    #pragma unroll
    for (int c = 0; c < NCLS; c++) acc[c] = 0.0f;

    const float* row = &g_O1[(size_t)n * HID];
    #pragma unroll
    for (int jq = 0; jq < HID / 4; jq++) {
        float4 r = *(const float4*)&row[jq * 4];
        float tv[4];
        tv[0] = fmaxf(r.x + bs[jq * 4 + 0], 0.f);
        tv[1] = fmaxf(r.y + bs[jq * 4 + 1], 0.f);
        tv[2] = fmaxf(r.z + bs[jq * 4 + 2], 0.f);
        tv[3] = fmaxf(r.w + bs[jq * 4 + 3], 0.f);
        #pragma unroll
        for (int u = 0; u < 4; u++) {
            int j = jq * 4 + u;
            float tvu = tv[u];
            #pragma unroll
            for (int cq = 0; cq < 4; cq++) {
                float4 w = *(const float4*)&Ws[j * NCLS + cq * 4];
                acc[cq * 4 + 0] += tvu * w.x;
                acc[cq * 4 + 1] += tvu * w.y;
                acc[cq * 4 + 2] += tvu * w.z;
                acc[cq * 4 + 3] += tvu * w.w;
            }
        }
    }

    float d  = g_dis[n];
    float sn = d * d;
    uint32_t* h2row = &g_H2b[(size_t)n * (NCLS / 2)];
    #pragma unroll
    for (int cq = 0; cq < 4; cq++) {
        float4 v = make_float4(acc[cq*4+0], acc[cq*4+1], acc[cq*4+2], acc[cq*4+3]);
        uint2 pk = make_uint2(bf16x2(v.y, v.x), bf16x2(v.w, v.z));
        *(uint2*)&h2row[cq * 2] = pk;
        float4 o = make_float4(v.x * sn, v.y * sn, v.z * sn, v.w * sn);
        *(float4*)&g_O2[(size_t)n * NCLS + cq * 4] = o;
    }
}

// ---------------- edge aggregation, 16 features (2 lanes per edge) ---------
__global__ __launch_bounds__(256)
void k_agg16(const int* __restrict__ src, const int* __restrict__ dst, int E) {
    int t = blockIdx.x * blockDim.x + threadIdx.x;
    int e = t >> 1;
    if (e >= E) return;
    int lane = t & 1;
    int s = src[e];
    int d = dst[e];
    float nr = g_norm[e];
    uint4 p = *(const uint4*)&g_H2b[(size_t)s * (NCLS / 2) + lane * 4];
    float* base = &g_O2[(size_t)d * NCLS + lane * 8];
    red_add_v4(base,     bf_lo(p.x) * nr, bf_hi(p.x) * nr, bf_lo(p.y) * nr, bf_hi(p.y) * nr);
    red_add_v4(base + 4, bf_lo(p.z) * nr, bf_hi(p.z) * nr, bf_lo(p.w) * nr, bf_hi(p.w) * nr);
}

// ---------------- final: out = log_softmax(O2 + b2) ------------------------
__global__ __launch_bounds__(256)
void k_lsm(const float* __restrict__ b2, float* __restrict__ out, int Nn) {
    __shared__ float bs[NCLS];
    if (threadIdx.x < NCLS) bs[threadIdx.x] = b2[threadIdx.x];
    __syncthreads();

    int n = blockIdx.x * blockDim.x + threadIdx.x;
    if (n >= Nn) return;

    float v[NCLS];
    #pragma unroll
    for (int cq = 0; cq < 4; cq++) {
        float4 r = *(const float4*)&g_O2[(size_t)n * NCLS + cq * 4];
        v[cq*4+0] = r.x + bs[cq*4+0];
        v[cq*4+1] = r.y + bs[cq*4+1];
        v[cq*4+2] = r.z + bs[cq*4+2];
        v[cq*4+3] = r.w + bs[cq*4+3];
    }
    float m = v[0];
    #pragma unroll
    for (int c = 1; c < NCLS; c++) m = fmaxf(m, v[c]);
    float s = 0.f;
    #pragma unroll
    for (int c = 0; c < NCLS; c++) s += expf(v[c] - m);
    float l = logf(s) + m;
    #pragma unroll
    for (int cq = 0; cq < 4; cq++) {
        float4 o = make_float4(v[cq*4+0]-l, v[cq*4+1]-l, v[cq*4+2]-l, v[cq*4+3]-l);
        *(float4*)&out[(size_t)n * NCLS + cq * 4] = o;
    }
}

// ---------------- launch ----------------------------------------------------
extern "C" void kernel_launch(void* const* d_in, const int* in_sizes, int n_in,
                              void* d_out, int out_size) {
    const float* x   = (const float*)d_in[0];   // [N, 512]
    const int*   ei  = (const int*)  d_in[1];   // [2, E]
    const float* ew  = (const float*)d_in[2];   // [E]
    const float* W1  = (const float*)d_in[3];   // [512, 64]
    const float* b1  = (const float*)d_in[4];   // [64]
    const float* W2  = (const float*)d_in[5];   // [64, 16]
    const float* b2  = (const float*)d_in[6];   // [16]
    float*       out = (float*)d_out;

    const int N = in_sizes[0] / INDIM;
    const int E = in_sizes[2];
    const int* src = ei;
    const int* dst = ei + E;

    const int T = 256;

    // 1: deg self-loop init + W1 bf16 transpose/pack (fused, independent ranges)
    k_prep<<<(N + T - 1) / T, T>>>(W1, N);
    // 2: weighted in-degree
    {
        int q = (E + 3) / 4;
        k_deg_acc<<<(q + T - 1) / T, T>>>(dst, ew, E);
    }
    // 3: deg -> rsqrt(deg)
    k_deg_fin<<<(N + T - 1) / T, T>>>(N);
    // 4: layer-1 GEMM (bf16 tensor pipe) — profiled slot
    k_gemm1_mma<<<(N + GM - 1) / GM, 256>>>(x, N);
    // 5: per-edge norm (independent of GEMM; needed only before agg64)
    {
        int q = (E + 7) / 8;
        k_norm<<<(q + T - 1) / T, T>>>(src, dst, ew, E);
    }
    // 6: layer-1 aggregation (bf16 gather, fp32 RED)
    {
        long long th = (long long)E * 8;
        k_agg64<<<(int)((th + T - 1) / T), T>>>(src, dst, E);
    }
    // 7: layer 2 dense
    k_layer2<<<(N + T - 1) / T, T>>>(b1, W2, N);
    // 8: layer-2 aggregation (bf16 gather, fp32 RED)
    {
        long long th = (long long)E * 2;
        k_agg16<<<(int)((th + T - 1) / T), T>>>(src, dst, E);
    }
    // 9: log-softmax epilogue
    k_lsm<<<(N + T - 1) / T, T>>>(b2, out, N);
}

// round 15
// speedup vs baseline: 1.1099x; 1.1099x over previous
#include <cuda_runtime.h>
#include <cstdint>

// Problem constants (fixed shapes for this problem instance).
#define NMAX   100000
#define EMAX   1600000
#define INDIM  512
#define HID    64
#define NCLS   16

// ---------------- scratch (device globals; no allocation allowed) ----------
__device__ __align__(256) float g_dis [NMAX];                    // deg -> rsqrt(deg)
__device__ __align__(256) float g_norm[EMAX];                    // per-edge norm
__device__ __align__(256) uint32_t g_Hb [(size_t)NMAX * HID / 2];  // x@W1, bf16x2 packed
__device__ __align__(256) float g_O1 [(size_t)NMAX * HID];       // aggregated layer-1 (fp32)
__device__ __align__(256) uint32_t g_H2b[(size_t)NMAX * NCLS / 2]; // relu(O1+b1)@W2, bf16x2
__device__ __align__(256) float g_O2 [(size_t)NMAX * NCLS];      // aggregated layer-2 (fp32)
// W1^T as packed bf16x2 over k-pairs: [n=0..63][kpair=0..255]
__device__ __align__(256) uint32_t g_Wbhi[(size_t)HID * INDIM / 2];

// pack two floats as bf16x2: result.lo16 = bf16(lo), result.hi16 = bf16(hi)
__device__ __forceinline__ uint32_t bf16x2(float hi, float lo) {
    uint32_t r;
    asm("cvt.rn.bf16x2.f32 %0, %1, %2;" : "=r"(r) : "f"(hi), "f"(lo));
    return r;
}
// unpack: lo element = bits<<16, hi element = bits&0xFFFF0000
__device__ __forceinline__ float bf_lo(uint32_t u) { return __uint_as_float(u << 16); }
__device__ __forceinline__ float bf_hi(uint32_t u) { return __uint_as_float(u & 0xFFFF0000u); }

// ---------------- prep: deg init (self-loop) + W1 bf16 transpose/pack ------
__global__ void k_prep(const float* __restrict__ W1, int n) {
    int i = blockIdx.x * blockDim.x + threadIdx.x;
    if (i < n) g_dis[i] = 1.0f;                       // self-loop weight
    if (i < HID * INDIM / 2) {                        // W1^T bf16 packed
        int c  = i >> 8;                              // output column 0..63
        int kp = i & 255;                             // k-pair 0..255
        float v0 = W1[(size_t)(2 * kp)     * HID + c];
        float v1 = W1[(size_t)(2 * kp + 1) * HID + c];
        g_Wbhi[i] = bf16x2(v1, v0);
    }
}

__global__ void k_deg_acc(const int* __restrict__ dst, const float* __restrict__ w, int E) {
    int q = blockIdx.x * blockDim.x + threadIdx.x;
    int base = q * 4;
    if (base + 3 < E) {
        int4   d = *(const int4*)&dst[base];
        float4 v = *(const float4*)&w[base];
        atomicAdd(&g_dis[d.x], v.x);
        atomicAdd(&g_dis[d.y], v.y);
        atomicAdd(&g_dis[d.z], v.z);
        atomicAdd(&g_dis[d.w], v.w);
    } else {
        for (int e = base; e < E; e++) atomicAdd(&g_dis[dst[e]], w[e]);
    }
}

__global__ void k_deg_fin(int n) {
    int i = blockIdx.x * blockDim.x + threadIdx.x;
    if (i < n) g_dis[i] = rsqrtf(g_dis[i]);
}

// 8 edges per thread: 16 independent L2 gathers in flight (latency-bound kernel)
__global__ void k_norm(const int* __restrict__ src, const int* __restrict__ dst,
                       const float* __restrict__ w, int E) {
    int q = blockIdx.x * blockDim.x + threadIdx.x;
    int base = q * 8;
    if (base + 7 < E) {
        int4   s0 = *(const int4*)&src[base];
        int4   s1 = *(const int4*)&src[base + 4];
        int4   d0 = *(const int4*)&dst[base];
        int4   d1 = *(const int4*)&dst[base + 4];
        float4 v0 = *(const float4*)&w[base];
        float4 v1 = *(const float4*)&w[base + 4];
        float a0 = g_dis[s0.x], a1 = g_dis[s0.y], a2 = g_dis[s0.z], a3 = g_dis[s0.w];
        float a4 = g_dis[s1.x], a5 = g_dis[s1.y], a6 = g_dis[s1.z], a7 = g_dis[s1.w];
        float b0 = g_dis[d0.x], b1 = g_dis[d0.y], b2 = g_dis[d0.z], b3 = g_dis[d0.w];
        float b4 = g_dis[d1.x], b5 = g_dis[d1.y], b6 = g_dis[d1.z], b7 = g_dis[d1.w];
        float4 o0 = make_float4(a0 * v0.x * b0, a1 * v0.y * b1, a2 * v0.z * b2, a3 * v0.w * b3);
        float4 o1 = make_float4(a4 * v1.x * b4, a5 * v1.y * b5, a6 * v1.z * b6, a7 * v1.w * b7);
        *(float4*)&g_norm[base]     = o0;
        *(float4*)&g_norm[base + 4] = o1;
    } else {
        for (int e = base; e < E; e++) g_norm[e] = g_dis[src[e]] * w[e] * g_dis[dst[e]];
    }
}

// ---------------- GEMM1 via mma.sync bf16 m16n8k16 (1-term, pure bf16) -----
// D[128,64] = bf16(A)[128,512] * bf16(B)[64,512]^T, fp32 accum.
// 256 threads = 8 warps as 4(m) x 2(n); warp tile 32x32 = 2x4 mma tiles of 16x8.
// Smem rows padded to 12 words: fragment pattern gid*12 + tig(+4) is
// bank-conflict-free (12g+t mod 32 distinct for g<8, t<8).
// Double-buffered: LDG(c+1) -> compute(c) -> STS(c+1), 1 syncthreads/chunk.
#define GM  128
#define NCH (INDIM / 16)           // 32 chunks of k=16

__device__ __forceinline__ void mma_bf16(float* c, const uint32_t* a, const uint32_t* b) {
    asm volatile(
        "mma.sync.aligned.m16n8k16.row.col.f32.bf16.bf16.f32 "
        "{%0,%1,%2,%3}, {%4,%5,%6,%7}, {%8,%9}, {%0,%1,%2,%3};"
        : "+f"(c[0]), "+f"(c[1]), "+f"(c[2]), "+f"(c[3])
        : "r"(a[0]), "r"(a[1]), "r"(a[2]), "r"(a[3]), "r"(b[0]), "r"(b[1]));
}

__global__ __launch_bounds__(256)
void k_gemm1_mma(const float* __restrict__ X, int Nrows) {
    __shared__ uint32_t Ah[2][GM][12];
    __shared__ uint32_t Bh[2][HID][12];

    const int tid  = threadIdx.x;
    const int lane = tid & 31;
    const int wid  = tid >> 5;
    const int wm   = wid >> 1;          // 0..3
    const int wn   = wid & 1;           // 0..1
    const int gid  = lane >> 2;         // groupID
    const int tig  = lane & 3;          // threadID in group
    const int rowBase = blockIdx.x * GM;

    // staging geometry (chunk-independent)
    const int ra = tid >> 2;            // A row for p=0 (p=1: +64)
    const int kq = tid & 3;             // float4 slot within k16
    const int rb = tid >> 2;            // B row 0..63
    const int pg = tid & 3;             // B k-pair group (2 pairs each)

    float C[2][4][4];
    #pragma unroll
    for (int mt = 0; mt < 2; mt++)
        #pragma unroll
        for (int nt = 0; nt < 4; nt++)
            #pragma unroll
            for (int q = 0; q < 4; q++) C[mt][nt][q] = 0.0f;

    float4 va[2];
    uint2  vbh;

    // ---- prologue: load + stage chunk 0 ----
    #pragma unroll
    for (int p = 0; p < 2; p++) {
        int grow = rowBase + ra + p * 64;
        va[p] = make_float4(0.f, 0.f, 0.f, 0.f);
        if (grow < Nrows) va[p] = *(const float4*)&X[(size_t)grow * INDIM + kq * 4];
    }
    vbh = *(const uint2*)&g_Wbhi[(size_t)rb * (INDIM / 2) + pg * 2];
    #pragma unroll
    for (int p = 0; p < 2; p++) {
        uint32_t h0 = bf16x2(va[p].y, va[p].x);
        uint32_t h1 = bf16x2(va[p].w, va[p].z);
        *(uint2*)&Ah[0][ra + p * 64][kq * 2] = make_uint2(h0, h1);
    }
    *(uint2*)&Bh[0][rb][pg * 2] = vbh;
    __syncthreads();

    for (int c = 0; c < NCH; c++) {
        const int buf = c & 1;
        // ---- prefetch chunk c+1 into registers ----
        if (c + 1 < NCH) {
            const int k0n = (c + 1) * 16;
            #pragma unroll
            for (int p = 0; p < 2; p++) {
                int grow = rowBase + ra + p * 64;
                va[p] = make_float4(0.f, 0.f, 0.f, 0.f);
                if (grow < Nrows)
                    va[p] = *(const float4*)&X[(size_t)grow * INDIM + k0n + kq * 4];
            }
            vbh = *(const uint2*)&g_Wbhi[(size_t)rb * (INDIM / 2) + (c + 1) * 8 + pg * 2];
        }

        // ---- compute chunk c ----
        {
            const uint32_t (*pA)[12] = Ah[buf];
            const uint32_t (*pBh)[12] = Bh[buf];
            uint32_t ah[2][4];
            #pragma unroll
            for (int mt = 0; mt < 2; mt++) {
                int r0 = wm * 32 + mt * 16 + gid;
                ah[mt][0] = pA[r0][tig];
                ah[mt][1] = pA[r0 + 8][tig];
                ah[mt][2] = pA[r0][tig + 4];
                ah[mt][3] = pA[r0 + 8][tig + 4];
            }
            uint32_t bhf[4][2];
            #pragma unroll
            for (int nt = 0; nt < 4; nt++) {
                int cb = wn * 32 + nt * 8 + gid;
                bhf[nt][0] = pBh[cb][tig]; bhf[nt][1] = pBh[cb][tig + 4];
            }
            #pragma unroll
            for (int mt = 0; mt < 2; mt++)
                #pragma unroll
                for (int nt = 0; nt < 4; nt++)
                    mma_bf16(C[mt][nt], ah[mt], bhf[nt]);
        }

        // ---- stage chunk c+1 ----
        if (c + 1 < NCH) {
            const int nb = buf ^ 1;
            #pragma unroll
            for (int p = 0; p < 2; p++) {
                uint32_t h0 = bf16x2(va[p].y, va[p].x);
                uint32_t h1 = bf16x2(va[p].w, va[p].z);
                *(uint2*)&Ah[nb][ra + p * 64][kq * 2] = make_uint2(h0, h1);
            }
            *(uint2*)&Bh[nb][rb][pg * 2] = vbh;
        }
        __syncthreads();
    }

    // ---- epilogue: Hb (bf16 packed) and O1 = H * dis^2 (self-loop init) ----
    #pragma unroll
    for (int mt = 0; mt < 2; mt++) {
        int r0 = rowBase + wm * 32 + mt * 16 + gid;
        int r1 = r0 + 8;
        if (r0 < Nrows) {
            float d = g_dis[r0]; float sn = d * d;
            uint32_t* hrow = &g_Hb[(size_t)r0 * (HID / 2)];
            float*    orow = &g_O1[(size_t)r0 * HID];
            #pragma unroll
            for (int nt = 0; nt < 4; nt++) {
                int col = wn * 32 + nt * 8 + tig * 2;
                float2 v = make_float2(C[mt][nt][0], C[mt][nt][1]);
                hrow[col >> 1] = bf16x2(v.y, v.x);
                *(float2*)&orow[col] = make_float2(v.x * sn, v.y * sn);
            }
        }
        if (r1 < Nrows) {
            float d = g_dis[r1]; float sn = d * d;
            uint32_t* hrow = &g_Hb[(size_t)r1 * (HID / 2)];
            float*    orow = &g_O1[(size_t)r1 * HID];
            #pragma unroll
            for (int nt = 0; nt < 4; nt++) {
                int col = wn * 32 + nt * 8 + tig * 2;
                float2 v = make_float2(C[mt][nt][2], C[mt][nt][3]);
                hrow[col >> 1] = bf16x2(v.y, v.x);
                *(float2*)&orow[col] = make_float2(v.x * sn, v.y * sn);
            }
        }
    }
}

// ---------------- edge aggregation, 64 features (16 lanes per edge) --------
// Each lane: uint2 gather (4 bf16 features, 8B) + ONE red.v4 (16B fp32).
__device__ __forceinline__ void red_add_v4(float* addr, float a, float b, float c, float d) {
    asm volatile("red.global.add.v4.f32 [%0], {%1, %2, %3, %4};"
                 :: "l"(addr), "f"(a), "f"(b), "f"(c), "f"(d) : "memory");
}

__global__ __launch_bounds__(256)
void k_agg64(const int* __restrict__ src, const int* __restrict__ dst, int E) {
    int t = blockIdx.x * blockDim.x + threadIdx.x;
    int e = t >> 4;
    if (e >= E) return;
    int lane = t & 15;
    int s = src[e];
    int d = dst[e];
    float nr = g_norm[e];
    uint2 p = *(const uint2*)&g_Hb[(size_t)s * (HID / 2) + lane * 2];
    red_add_v4(&g_O1[(size_t)d * HID + lane * 4],
               bf_lo(p.x) * nr, bf_hi(p.x) * nr, bf_lo(p.y) * nr, bf_hi(p.y) * nr);
}

// ---------------- layer 2: H2 = relu(O1+b1) @ W2 ; O2 = H2 * selfnorm ------
__global__ __launch_bounds__(256)
void k_layer2(const float* __restrict__ b1, const float* __restrict__ W2, int Nn) {
    __shared__ float Ws[HID * NCLS];
    __shared__ float bs[HID];
    for (int i = threadIdx.x; i < HID * NCLS; i += blockDim.x) Ws[i] = W2[i];
    if (threadIdx.x < HID) bs[threadIdx.x] = b1[threadIdx.x];
    __syncthreads();

    int n = blockIdx.x * blockDim.x + threadIdx.x;
    if (n >= Nn) return;

    float acc[NCLS];
    #pragma unroll
    for (int c = 0; c < NCLS; c++) acc[c] = 0.0f;

    const float* row = &g_O1[(size_t)n * HID];
    #pragma unroll
    for (int jq = 0; jq < HID / 4; jq++) {
        float4 r = *(const float4*)&row[jq * 4];
        float tv[4];
        tv[0] = fmaxf(r.x + bs[jq * 4 + 0], 0.f);
        tv[1] = fmaxf(r.y + bs[jq * 4 + 1], 0.f);
        tv[2] = fmaxf(r.z + bs[jq * 4 + 2], 0.f);
        tv[3] = fmaxf(r.w + bs[jq * 4 + 3], 0.f);
        #pragma unroll
        for (int u = 0; u < 4; u++) {
            int j = jq * 4 + u;
            float tvu = tv[u];
            #pragma unroll
            for (int cq = 0; cq < 4; cq++) {
                float4 w = *(const float4*)&Ws[j * NCLS + cq * 4];
                acc[cq * 4 + 0] += tvu * w.x;
                acc[cq * 4 + 1] += tvu * w.y;
                acc[cq * 4 + 2] += tvu * w.z;
                acc[cq * 4 + 3] += tvu * w.w;
            }
        }
    }

    float d  = g_dis[n];
    float sn = d * d;
    uint32_t* h2row = &g_H2b[(size_t)n * (NCLS / 2)];
    #pragma unroll
    for (int cq = 0; cq < 4; cq++) {
        float4 v = make_float4(acc[cq*4+0], acc[cq*4+1], acc[cq*4+2], acc[cq*4+3]);
        uint2 pk = make_uint2(bf16x2(v.y, v.x), bf16x2(v.w, v.z));
        *(uint2*)&h2row[cq * 2] = pk;
        float4 o = make_float4(v.x * sn, v.y * sn, v.z * sn, v.w * sn);
        *(float4*)&g_O2[(size_t)n * NCLS + cq * 4] = o;
    }
}

// ---------------- edge aggregation, 16 features (4 lanes per edge) ---------
__global__ __launch_bounds__(256)
void k_agg16(const int* __restrict__ src, const int* __restrict__ dst, int E) {
    int t = blockIdx.x * blockDim.x + threadIdx.x;
    int e = t >> 2;
    if (e >= E) return;
    int lane = t & 3;
    int s = src[e];
    int d = dst[e];
    float nr = g_norm[e];
    uint2 p = *(const uint2*)&g_H2b[(size_t)s * (NCLS / 2) + lane * 2];
    red_add_v4(&g_O2[(size_t)d * NCLS + lane * 4],
               bf_lo(p.x) * nr, bf_hi(p.x) * nr, bf_lo(p.y) * nr, bf_hi(p.y) * nr);
}

// ---------------- final: out = log_softmax(O2 + b2) ------------------------
__global__ __launch_bounds__(256)
void k_lsm(const float* __restrict__ b2, float* __restrict__ out, int Nn) {
    __shared__ float bs[NCLS];
    if (threadIdx.x < NCLS) bs[threadIdx.x] = b2[threadIdx.x];
    __syncthreads();

    int n = blockIdx.x * blockDim.x + threadIdx.x;
    if (n >= Nn) return;

    float v[NCLS];
    #pragma unroll
    for (int cq = 0; cq < 4; cq++) {
        float4 r = *(const float4*)&g_O2[(size_t)n * NCLS + cq * 4];
        v[cq*4+0] = r.x + bs[cq*4+0];
        v[cq*4+1] = r.y + bs[cq*4+1];
        v[cq*4+2] = r.z + bs[cq*4+2];
        v[cq*4+3] = r.w + bs[cq*4+3];
    }
    float m = v[0];
    #pragma unroll
    for (int c = 1; c < NCLS; c++) m = fmaxf(m, v[c]);
    float s = 0.f;
    #pragma unroll
    for (int c = 0; c < NCLS; c++) s += expf(v[c] - m);
    float l = logf(s) + m;
    #pragma unroll
    for (int cq = 0; cq < 4; cq++) {
        float4 o = make_float4(v[cq*4+0]-l, v[cq*4+1]-l, v[cq*4+2]-l, v[cq*4+3]-l);
        *(float4*)&out[(size_t)n * NCLS + cq * 4] = o;
    }
}

// ---------------- launch ----------------------------------------------------
extern "C" void kernel_launch(void* const* d_in, const int* in_sizes, int n_in,
                              void* d_out, int out_size) {
    const float* x   = (const float*)d_in[0];   // [N, 512]
    const int*   ei  = (const int*)  d_in[1];   // [2, E]
    const float* ew  = (const float*)d_in[2];   // [E]
    const float* W1  = (const float*)d_in[3];   // [512, 64]
    const float* b1  = (const float*)d_in[4];   // [64]
    const float* W2  = (const float*)d_in[5];   // [64, 16]
    const float* b2  = (const float*)d_in[6];   // [16]
    float*       out = (float*)d_out;

    const int N = in_sizes[0] / INDIM;
    const int E = in_sizes[2];
    const int* src = ei;
    const int* dst = ei + E;

    const int T = 256;

    // 1: deg self-loop init + W1 bf16 transpose/pack (fused, independent ranges)
    k_prep<<<(N + T - 1) / T, T>>>(W1, N);
    // 2: weighted in-degree
    {
        int q = (E + 3) / 4;
        k_deg_acc<<<(q + T - 1) / T, T>>>(dst, ew, E);
    }
    // 3: deg -> rsqrt(deg)
    k_deg_fin<<<(N + T - 1) / T, T>>>(N);
    // 4: layer-1 GEMM (bf16 tensor pipe) — profiled slot
    k_gemm1_mma<<<(N + GM - 1) / GM, 256>>>(x, N);
    // 5: per-edge norm (independent of GEMM; needed only before agg64)
    {
        int q = (E + 7) / 8;
        k_norm<<<(q + T - 1) / T, T>>>(src, dst, ew, E);
    }
    // 6: layer-1 aggregation (bf16 uint2 gather, 1 fp32 RED per lane)
    {
        long long th = (long long)E * 16;
        k_agg64<<<(int)((th + T - 1) / T), T>>>(src, dst, E);
    }
    // 7: layer 2 dense
    k_layer2<<<(N + T - 1) / T, T>>>(b1, W2, N);
    // 8: layer-2 aggregation (bf16 uint2 gather, 1 fp32 RED per lane)
    {
        long long th = (long long)E * 4;
        k_agg16<<<(int)((th + T - 1) / T), T>>>(src, dst, E);
    }
    // 9: log-softmax epilogue
    k_lsm<<<(N + T - 1) / T, T>>>(b2, out, N);
}

// round 16
// speedup vs baseline: 1.3717x; 1.2358x over previous
#include <cuda_runtime.h>
#include <cstdint>

// Problem constants (fixed shapes for this problem instance).
#define NMAX   100000
#define EMAX   1600000
#define INDIM  512
#define HID    64
#define NCLS   16

// ---------------- scratch (device globals; no allocation allowed) ----------
__device__ __align__(256) float g_dis [NMAX];                      // deg -> rsqrt(deg)
__device__ __align__(256) int   g_cnt [NMAX];                      // in-degree counts
__device__ __align__(256) int   g_rowptr[NMAX + 1];                // CSR row pointers
__device__ __align__(256) int   g_cur [NMAX];                      // scatter cursors
__device__ __align__(256) int   g_btot[512];                       // scan block totals
__device__ __align__(256) int   g_boff[512];                       // scan block offsets
__device__ __align__(256) int2  g_edge[EMAX];                      // CSR edges: (src, norm bits)
__device__ __align__(256) uint32_t g_Hb [(size_t)NMAX * HID / 2];  // x@W1, bf16x2 packed
__device__ __align__(256) float g_O1 [(size_t)NMAX * HID];         // aggregated layer-1 (fp32)
__device__ __align__(256) uint32_t g_H2b[(size_t)NMAX * NCLS / 2]; // relu(O1+b1)@W2, bf16x2
__device__ __align__(256) float g_O2 [(size_t)NMAX * NCLS];        // aggregated layer-2 (fp32)
// W1^T as packed bf16x2 over k-pairs: [n=0..63][kpair=0..255]
__device__ __align__(256) uint32_t g_Wbhi[(size_t)HID * INDIM / 2];

// pack two floats as bf16x2: result.lo16 = bf16(lo), result.hi16 = bf16(hi)
__device__ __forceinline__ uint32_t bf16x2(float hi, float lo) {
    uint32_t r;
    asm("cvt.rn.bf16x2.f32 %0, %1, %2;" : "=r"(r) : "f"(hi), "f"(lo));
    return r;
}
// unpack: lo element = bits<<16, hi element = bits&0xFFFF0000
__device__ __forceinline__ float bf_lo(uint32_t u) { return __uint_as_float(u << 16); }
__device__ __forceinline__ float bf_hi(uint32_t u) { return __uint_as_float(u & 0xFFFF0000u); }

// ---------------- prep: deg/cnt init + W1 bf16 transpose/pack --------------
__global__ void k_prep(const float* __restrict__ W1, int n) {
    int i = blockIdx.x * blockDim.x + threadIdx.x;
    if (i < n) { g_dis[i] = 1.0f; g_cnt[i] = 0; }     // self-loop weight, zero histogram
    if (i < HID * INDIM / 2) {                        // W1^T bf16 packed
        int c  = i >> 8;                              // output column 0..63
        int kp = i & 255;                             // k-pair 0..255
        float v0 = W1[(size_t)(2 * kp)     * HID + c];
        float v1 = W1[(size_t)(2 * kp + 1) * HID + c];
        g_Wbhi[i] = bf16x2(v1, v0);
    }
}

// weighted in-degree (for norm) + integer in-degree (for CSR)
__global__ void k_deg_acc(const int* __restrict__ dst, const float* __restrict__ w, int E) {
    int q = blockIdx.x * blockDim.x + threadIdx.x;
    int base = q * 4;
    if (base + 3 < E) {
        int4   d = *(const int4*)&dst[base];
        float4 v = *(const float4*)&w[base];
        atomicAdd(&g_dis[d.x], v.x); atomicAdd(&g_cnt[d.x], 1);
        atomicAdd(&g_dis[d.y], v.y); atomicAdd(&g_cnt[d.y], 1);
        atomicAdd(&g_dis[d.z], v.z); atomicAdd(&g_cnt[d.z], 1);
        atomicAdd(&g_dis[d.w], v.w); atomicAdd(&g_cnt[d.w], 1);
    } else {
        for (int e = base; e < E; e++) {
            atomicAdd(&g_dis[dst[e]], w[e]);
            atomicAdd(&g_cnt[dst[e]], 1);
        }
    }
}

__global__ void k_deg_fin(int n) {
    int i = blockIdx.x * blockDim.x + threadIdx.x;
    if (i < n) g_dis[i] = rsqrtf(g_dis[i]);
}

// ---------------- 3-kernel exclusive scan of g_cnt -> g_rowptr -------------
__global__ void k_scan1(int n) {
    __shared__ int s[256];
    int t = threadIdx.x;
    int i = blockIdx.x * 256 + t;
    int v = (i < n) ? g_cnt[i] : 0;
    s[t] = v; __syncthreads();
    #pragma unroll
    for (int off = 1; off < 256; off <<= 1) {
        int x = (t >= off) ? s[t - off] : 0;
        __syncthreads();
        s[t] += x;
        __syncthreads();
    }
    if (i < n) g_rowptr[i] = s[t] - v;       // exclusive within block
    if (t == 255) g_btot[blockIdx.x] = s[255];
}

__global__ void k_scan2(int nb) {
    __shared__ int s[512];
    int t = threadIdx.x;
    int v = (t < nb) ? g_btot[t] : 0;
    s[t] = v; __syncthreads();
    #pragma unroll
    for (int off = 1; off < 512; off <<= 1) {
        int x = (t >= off) ? s[t - off] : 0;
        __syncthreads();
        s[t] += x;
        __syncthreads();
    }
    g_boff[t] = s[t] - v;                    // exclusive block offsets
}

__global__ void k_scan3(int n, int E) {
    int i = blockIdx.x * blockDim.x + threadIdx.x;
    if (i < n) {
        int r = g_rowptr[i] + g_boff[i >> 8];
        g_rowptr[i] = r;
        g_cur[i] = r;
    }
    if (i == 0) g_rowptr[n] = E;
}

// ---------------- norm + CSR scatter: g_edge[pos] = (src, norm) ------------
__global__ void k_norm_scatter(const int* __restrict__ src, const int* __restrict__ dst,
                               const float* __restrict__ w, int E) {
    int q = blockIdx.x * blockDim.x + threadIdx.x;
    int base = q * 4;
    if (base + 3 < E) {
        int4   s = *(const int4*)&src[base];
        int4   d = *(const int4*)&dst[base];
        float4 v = *(const float4*)&w[base];
        float n0 = g_dis[s.x] * v.x * g_dis[d.x];
        float n1 = g_dis[s.y] * v.y * g_dis[d.y];
        float n2 = g_dis[s.z] * v.z * g_dis[d.z];
        float n3 = g_dis[s.w] * v.w * g_dis[d.w];
        int p0 = atomicAdd(&g_cur[d.x], 1);
        int p1 = atomicAdd(&g_cur[d.y], 1);
        int p2 = atomicAdd(&g_cur[d.z], 1);
        int p3 = atomicAdd(&g_cur[d.w], 1);
        g_edge[p0] = make_int2(s.x, __float_as_int(n0));
        g_edge[p1] = make_int2(s.y, __float_as_int(n1));
        g_edge[p2] = make_int2(s.z, __float_as_int(n2));
        g_edge[p3] = make_int2(s.w, __float_as_int(n3));
    } else {
        for (int e = base; e < E; e++) {
            float nr = g_dis[src[e]] * w[e] * g_dis[dst[e]];
            int p = atomicAdd(&g_cur[dst[e]], 1);
            g_edge[p] = make_int2(src[e], __float_as_int(nr));
        }
    }
}

// ---------------- GEMM1 via mma.sync bf16 m16n8k16 (1-term, pure bf16) -----
// D[128,64] = bf16(A)[128,512] * bf16(B)[64,512]^T, fp32 accum.
// 256 threads = 8 warps as 4(m) x 2(n); warp tile 32x32 = 2x4 mma tiles of 16x8.
// Smem rows padded to 12 words: fragment pattern gid*12 + tig(+4) is
// bank-conflict-free (12g+t mod 32 distinct for g<8, t<8).
// Double-buffered: LDG(c+1) -> compute(c) -> STS(c+1), 1 syncthreads/chunk.
#define GM  128
#define NCH (INDIM / 16)           // 32 chunks of k=16

__device__ __forceinline__ void mma_bf16(float* c, const uint32_t* a, const uint32_t* b) {
    asm volatile(
        "mma.sync.aligned.m16n8k16.row.col.f32.bf16.bf16.f32 "
        "{%0,%1,%2,%3}, {%4,%5,%6,%7}, {%8,%9}, {%0,%1,%2,%3};"
        : "+f"(c[0]), "+f"(c[1]), "+f"(c[2]), "+f"(c[3])
        : "r"(a[0]), "r"(a[1]), "r"(a[2]), "r"(a[3]), "r"(b[0]), "r"(b[1]));
}

__global__ __launch_bounds__(256)
void k_gemm1_mma(const float* __restrict__ X, int Nrows) {
    __shared__ uint32_t Ah[2][GM][12];
    __shared__ uint32_t Bh[2][HID][12];

    const int tid  = threadIdx.x;
    const int lane = tid & 31;
    const int wid  = tid >> 5;
    const int wm   = wid >> 1;          // 0..3
    const int wn   = wid & 1;           // 0..1
    const int gid  = lane >> 2;         // groupID
    const int tig  = lane & 3;          // threadID in group
    const int rowBase = blockIdx.x * GM;

    // staging geometry (chunk-independent)
    const int ra = tid >> 2;            // A row for p=0 (p=1: +64)
    const int kq = tid & 3;             // float4 slot within k16
    const int rb = tid >> 2;            // B row 0..63
    const int pg = tid & 3;             // B k-pair group (2 pairs each)

    float C[2][4][4];
    #pragma unroll
    for (int mt = 0; mt < 2; mt++)
        #pragma unroll
        for (int nt = 0; nt < 4; nt++)
            #pragma unroll
            for (int q = 0; q < 4; q++) C[mt][nt][q] = 0.0f;

    float4 va[2];
    uint2  vbh;

    // ---- prologue: load + stage chunk 0 ----
    #pragma unroll
    for (int p = 0; p < 2; p++) {
        int grow = rowBase + ra + p * 64;
        va[p] = make_float4(0.f, 0.f, 0.f, 0.f);
        if (grow < Nrows) va[p] = *(const float4*)&X[(size_t)grow * INDIM + kq * 4];
    }
    vbh = *(const uint2*)&g_Wbhi[(size_t)rb * (INDIM / 2) + pg * 2];
    #pragma unroll
    for (int p = 0; p < 2; p++) {
        uint32_t h0 = bf16x2(va[p].y, va[p].x);
        uint32_t h1 = bf16x2(va[p].w, va[p].z);
        *(uint2*)&Ah[0][ra + p * 64][kq * 2] = make_uint2(h0, h1);
    }
    *(uint2*)&Bh[0][rb][pg * 2] = vbh;
    __syncthreads();

    for (int c = 0; c < NCH; c++) {
        const int buf = c & 1;
        // ---- prefetch chunk c+1 into registers ----
        if (c + 1 < NCH) {
            const int k0n = (c + 1) * 16;
            #pragma unroll
            for (int p = 0; p < 2; p++) {
                int grow = rowBase + ra + p * 64;
                va[p] = make_float4(0.f, 0.f, 0.f, 0.f);
                if (grow < Nrows)
                    va[p] = *(const float4*)&X[(size_t)grow * INDIM + k0n + kq * 4];
            }
            vbh = *(const uint2*)&g_Wbhi[(size_t)rb * (INDIM / 2) + (c + 1) * 8 + pg * 2];
        }

        // ---- compute chunk c ----
        {
            const uint32_t (*pA)[12] = Ah[buf];
            const uint32_t (*pBh)[12] = Bh[buf];
            uint32_t ah[2][4];
            #pragma unroll
            for (int mt = 0; mt < 2; mt++) {
                int r0 = wm * 32 + mt * 16 + gid;
                ah[mt][0] = pA[r0][tig];
                ah[mt][1] = pA[r0 + 8][tig];
                ah[mt][2] = pA[r0][tig + 4];
                ah[mt][3] = pA[r0 + 8][tig + 4];
            }
            uint32_t bhf[4][2];
            #pragma unroll
            for (int nt = 0; nt < 4; nt++) {
                int cb = wn * 32 + nt * 8 + gid;
                bhf[nt][0] = pBh[cb][tig]; bhf[nt][1] = pBh[cb][tig + 4];
            }
            #pragma unroll
            for (int mt = 0; mt < 2; mt++)
                #pragma unroll
                for (int nt = 0; nt < 4; nt++)
                    mma_bf16(C[mt][nt], ah[mt], bhf[nt]);
        }

        // ---- stage chunk c+1 ----
        if (c + 1 < NCH) {
            const int nb = buf ^ 1;
            #pragma unroll
            for (int p = 0; p < 2; p++) {
                uint32_t h0 = bf16x2(va[p].y, va[p].x);
                uint32_t h1 = bf16x2(va[p].w, va[p].z);
                *(uint2*)&Ah[nb][ra + p * 64][kq * 2] = make_uint2(h0, h1);
            }
            *(uint2*)&Bh[nb][rb][pg * 2] = vbh;
        }
        __syncthreads();
    }

    // ---- epilogue: Hb (bf16 packed) only; self-loop handled in agg64 ----
    #pragma unroll
    for (int mt = 0; mt < 2; mt++) {
        int r0 = rowBase + wm * 32 + mt * 16 + gid;
        int r1 = r0 + 8;
        if (r0 < Nrows) {
            uint32_t* hrow = &g_Hb[(size_t)r0 * (HID / 2)];
            #pragma unroll
            for (int nt = 0; nt < 4; nt++) {
                int col = wn * 32 + nt * 8 + tig * 2;
                hrow[col >> 1] = bf16x2(C[mt][nt][1], C[mt][nt][0]);
            }
        }
        if (r1 < Nrows) {
            uint32_t* hrow = &g_Hb[(size_t)r1 * (HID / 2)];
            #pragma unroll
            for (int nt = 0; nt < 4; nt++) {
                int col = wn * 32 + nt * 8 + tig * 2;
                hrow[col >> 1] = bf16x2(C[mt][nt][3], C[mt][nt][2]);
            }
        }
    }
}

// ---------------- CSR aggregation, 64 features (16 lanes per node) ---------
// Register accumulation, one plain STG.128 per lane. Zero atomics.
__global__ __launch_bounds__(256)
void k_agg64(int Nn) {
    int t = blockIdx.x * blockDim.x + threadIdx.x;
    int node = t >> 4;
    if (node >= Nn) return;
    int lane = t & 15;

    int beg = g_rowptr[node], end = g_rowptr[node + 1];
    float dis = g_dis[node];
    float sn  = dis * dis;

    // self-loop term
    uint2 h = *(const uint2*)&g_Hb[(size_t)node * (HID / 2) + lane * 2];
    float a0 = bf_lo(h.x) * sn, a1 = bf_hi(h.x) * sn;
    float a2 = bf_lo(h.y) * sn, a3 = bf_hi(h.y) * sn;

    int e = beg;
    for (; e + 3 < end; e += 4) {
        int2 e0 = g_edge[e], e1 = g_edge[e + 1], e2 = g_edge[e + 2], e3 = g_edge[e + 3];
        uint2 p0 = *(const uint2*)&g_Hb[(size_t)e0.x * (HID / 2) + lane * 2];
        uint2 p1 = *(const uint2*)&g_Hb[(size_t)e1.x * (HID / 2) + lane * 2];
        uint2 p2 = *(const uint2*)&g_Hb[(size_t)e2.x * (HID / 2) + lane * 2];
        uint2 p3 = *(const uint2*)&g_Hb[(size_t)e3.x * (HID / 2) + lane * 2];
        float n0 = __int_as_float(e0.y), n1 = __int_as_float(e1.y);
        float n2 = __int_as_float(e2.y), n3 = __int_as_float(e3.y);
        a0 += bf_lo(p0.x) * n0; a1 += bf_hi(p0.x) * n0; a2 += bf_lo(p0.y) * n0; a3 += bf_hi(p0.y) * n0;
        a0 += bf_lo(p1.x) * n1; a1 += bf_hi(p1.x) * n1; a2 += bf_lo(p1.y) * n1; a3 += bf_hi(p1.y) * n1;
        a0 += bf_lo(p2.x) * n2; a1 += bf_hi(p2.x) * n2; a2 += bf_lo(p2.y) * n2; a3 += bf_hi(p2.y) * n2;
        a0 += bf_lo(p3.x) * n3; a1 += bf_hi(p3.x) * n3; a2 += bf_lo(p3.y) * n3; a3 += bf_hi(p3.y) * n3;
    }
    for (; e < end; e++) {
        int2 ed = g_edge[e];
        uint2 p = *(const uint2*)&g_Hb[(size_t)ed.x * (HID / 2) + lane * 2];
        float nr = __int_as_float(ed.y);
        a0 += bf_lo(p.x) * nr; a1 += bf_hi(p.x) * nr;
        a2 += bf_lo(p.y) * nr; a3 += bf_hi(p.y) * nr;
    }

    *(float4*)&g_O1[(size_t)node * HID + lane * 4] = make_float4(a0, a1, a2, a3);
}

// ---------------- layer 2: H2 = relu(O1+b1) @ W2 (bf16 packed out) ---------
__global__ __launch_bounds__(256)
void k_layer2(const float* __restrict__ b1, const float* __restrict__ W2, int Nn) {
    __shared__ float Ws[HID * NCLS];
    __shared__ float bs[HID];
    for (int i = threadIdx.x; i < HID * NCLS; i += blockDim.x) Ws[i] = W2[i];
    if (threadIdx.x < HID) bs[threadIdx.x] = b1[threadIdx.x];
    __syncthreads();

    int n = blockIdx.x * blockDim.x + threadIdx.x;
    if (n >= Nn) return;

    float acc[NCLS];
    #pragma unroll
    for (int c = 0; c < NCLS; c++) acc[c] = 0.0f;

    const float* row = &g_O1[(size_t)n * HID];
    #pragma unroll
    for (int jq = 0; jq < HID / 4; jq++) {
        float4 r = *(const float4*)&row[jq * 4];
        float tv[4];
        tv[0] = fmaxf(r.x + bs[jq * 4 + 0], 0.f);
        tv[1] = fmaxf(r.y + bs[jq * 4 + 1], 0.f);
        tv[2] = fmaxf(r.z + bs[jq * 4 + 2], 0.f);
        tv[3] = fmaxf(r.w + bs[jq * 4 + 3], 0.f);
        #pragma unroll
        for (int u = 0; u < 4; u++) {
            int j = jq * 4 + u;
            float tvu = tv[u];
            #pragma unroll
            for (int cq = 0; cq < 4; cq++) {
                float4 w = *(const float4*)&Ws[j * NCLS + cq * 4];
                acc[cq * 4 + 0] += tvu * w.x;
                acc[cq * 4 + 1] += tvu * w.y;
                acc[cq * 4 + 2] += tvu * w.z;
                acc[cq * 4 + 3] += tvu * w.w;
            }
        }
    }

    uint32_t* h2row = &g_H2b[(size_t)n * (NCLS / 2)];
    #pragma unroll
    for (int cq = 0; cq < 4; cq++) {
        uint2 pk = make_uint2(bf16x2(acc[cq*4+1], acc[cq*4+0]),
                              bf16x2(acc[cq*4+3], acc[cq*4+2]));
        *(uint2*)&h2row[cq * 2] = pk;
    }
}

// ---------------- CSR aggregation, 16 features (4 lanes per node) ----------
__global__ __launch_bounds__(256)
void k_agg16(int Nn) {
    int t = blockIdx.x * blockDim.x + threadIdx.x;
    int node = t >> 2;
    if (node >= Nn) return;
    int lane = t & 3;

    int beg = g_rowptr[node], end = g_rowptr[node + 1];
    float dis = g_dis[node];
    float sn  = dis * dis;

    uint2 h = *(const uint2*)&g_H2b[(size_t)node * (NCLS / 2) + lane * 2];
    float a0 = bf_lo(h.x) * sn, a1 = bf_hi(h.x) * sn;
    float a2 = bf_lo(h.y) * sn, a3 = bf_hi(h.y) * sn;

    int e = beg;
    for (; e + 3 < end; e += 4) {
        int2 e0 = g_edge[e], e1 = g_edge[e + 1], e2 = g_edge[e + 2], e3 = g_edge[e + 3];
        uint2 p0 = *(const uint2*)&g_H2b[(size_t)e0.x * (NCLS / 2) + lane * 2];
        uint2 p1 = *(const uint2*)&g_H2b[(size_t)e1.x * (NCLS / 2) + lane * 2];
        uint2 p2 = *(const uint2*)&g_H2b[(size_t)e2.x * (NCLS / 2) + lane * 2];
        uint2 p3 = *(const uint2*)&g_H2b[(size_t)e3.x * (NCLS / 2) + lane * 2];
        float n0 = __int_as_float(e0.y), n1 = __int_as_float(e1.y);
        float n2 = __int_as_float(e2.y), n3 = __int_as_float(e3.y);
        a0 += bf_lo(p0.x) * n0; a1 += bf_hi(p0.x) * n0; a2 += bf_lo(p0.y) * n0; a3 += bf_hi(p0.y) * n0;
        a0 += bf_lo(p1.x) * n1; a1 += bf_hi(p1.x) * n1; a2 += bf_lo(p1.y) * n1; a3 += bf_hi(p1.y) * n1;
        a0 += bf_lo(p2.x) * n2; a1 += bf_hi(p2.x) * n2; a2 += bf_lo(p2.y) * n2; a3 += bf_hi(p2.y) * n2;
        a0 += bf_lo(p3.x) * n3; a1 += bf_hi(p3.x) * n3; a2 += bf_lo(p3.y) * n3; a3 += bf_hi(p3.y) * n3;
    }
    for (; e < end; e++) {
        int2 ed = g_edge[e];
        uint2 p = *(const uint2*)&g_H2b[(size_t)ed.x * (NCLS / 2) + lane * 2];
        float nr = __int_as_float(ed.y);
        a0 += bf_lo(p.x) * nr; a1 += bf_hi(p.x) * nr;
        a2 += bf_lo(p.y) * nr; a3 += bf_hi(p.y) * nr;
    }

    *(float4*)&g_O2[(size_t)node * NCLS + lane * 4] = make_float4(a0, a1, a2, a3);
}

// ---------------- final: out = log_softmax(O2 + b2) ------------------------
__global__ __launch_bounds__(256)
void k_lsm(const float* __restrict__ b2, float* __restrict__ out, int Nn) {
    __shared__ float bs[NCLS];
    if (threadIdx.x < NCLS) bs[threadIdx.x] = b2[threadIdx.x];
    __syncthreads();

    int n = blockIdx.x * blockDim.x + threadIdx.x;
    if (n >= Nn) return;

    float v[NCLS];
    #pragma unroll
    for (int cq = 0; cq < 4; cq++) {
        float4 r = *(const float4*)&g_O2[(size_t)n * NCLS + cq * 4];
        v[cq*4+0] = r.x + bs[cq*4+0];
        v[cq*4+1] = r.y + bs[cq*4+1];
        v[cq*4+2] = r.z + bs[cq*4+2];
        v[cq*4+3] = r.w + bs[cq*4+3];
    }
    float m = v[0];
    #pragma unroll
    for (int c = 1; c < NCLS; c++) m = fmaxf(m, v[c]);
    float s = 0.f;
    #pragma unroll
    for (int c = 0; c < NCLS; c++) s += expf(v[c] - m);
    float l = logf(s) + m;
    #pragma unroll
    for (int cq = 0; cq < 4; cq++) {
        float4 o = make_float4(v[cq*4+0]-l, v[cq*4+1]-l, v[cq*4+2]-l, v[cq*4+3]-l);
        *(float4*)&out[(size_t)n * NCLS + cq * 4] = o;
    }
}

// ---------------- launch ----------------------------------------------------
extern "C" void kernel_launch(void* const* d_in, const int* in_sizes, int n_in,
                              void* d_out, int out_size) {
    const float* x   = (const float*)d_in[0];   // [N, 512]
    const int*   ei  = (const int*)  d_in[1];   // [2, E]
    const float* ew  = (const float*)d_in[2];   // [E]
    const float* W1  = (const float*)d_in[3];   // [512, 64]
    const float* b1  = (const float*)d_in[4];   // [64]
    const float* W2  = (const float*)d_in[5];   // [64, 16]
    const float* b2  = (const float*)d_in[6];   // [16]
    float*       out = (float*)d_out;

    const int N = in_sizes[0] / INDIM;
    const int E = in_sizes[2];
    const int* src = ei;
    const int* dst = ei + E;

    const int T = 256;
    const int NB = (N + 255) / 256;             // scan blocks (<= 391)

    // 1: deg/cnt init + W1 bf16 pack
    k_prep<<<(N + T - 1) / T, T>>>(W1, N);
    // 2: weighted in-degree + integer counts
    {
        int q = (E + 3) / 4;
        k_deg_acc<<<(q + T - 1) / T, T>>>(dst, ew, E);
    }
    // 3: deg -> rsqrt(deg)
    k_deg_fin<<<(N + T - 1) / T, T>>>(N);
    // 4: layer-1 GEMM (bf16 tensor pipe) — profiled slot
    k_gemm1_mma<<<(N + GM - 1) / GM, 256>>>(x, N);
    // 5-7: exclusive scan of counts -> rowptr (+ cursor init)
    k_scan1<<<NB, 256>>>(N);
    k_scan2<<<1, 512>>>(NB);
    k_scan3<<<NB, 256>>>(N, E);
    // 8: per-edge norm + CSR scatter
    {
        int q = (E + 3) / 4;
        k_norm_scatter<<<(q + T - 1) / T, T>>>(src, dst, ew, E);
    }
    // 9: layer-1 aggregation (CSR gather, register accumulate, plain stores)
    {
        long long th = (long long)N * 16;
        k_agg64<<<(int)((th + T - 1) / T), T>>>(N);
    }
    // 10: layer 2 dense
    k_layer2<<<(N + T - 1) / T, T>>>(b1, W2, N);
    // 11: layer-2 aggregation (CSR gather)
    {
        long long th = (long long)N * 4;
        k_agg16<<<(int)((th + T - 1) / T), T>>>(N);
    }
    // 12: log-softmax epilogue
    k_lsm<<<(N + T - 1) / T, T>>>(b2, out, N);
}